// round 4
// baseline (speedup 1.0000x reference)
#include <cuda_runtime.h>

// Problem constants (fixed shapes from reference)
#define B_  32
#define C_  64
#define H_  112
#define MH_ 28      // coarse grid = H/4
#define G_  4

// Scratch (no cudaMalloc allowed).
__device__ unsigned char gA[B_ * MH_ * MH_];          // coarse any-group mask
__device__ unsigned int  g_cnt_mask[B_ * MH_];        // per (b,i) coarse mask count
__device__ unsigned int  g_cnt_dil [B_ * H_];         // per (b,h) fine dil count

// One CTA per (b, coarse-row i). 256 threads.
//  Phase 1: 4x4 avg-pool of x[b, :, 4i..4i+3, :] -> sm[64][28]   (float4 coalesced reads)
//  Phase 2: 8x64 GEMV per coarse cell -> logits[8][28]
//  Phase 3: gumbel argmax -> coarse mask M[4][28]; OR-map row -> gA; count -> slot
//  Phase 4: write fine mask rows 4i..4i+3 for all 4 groups (float4 stores)
__global__ __launch_bounds__(256)
void k_pool_mask(const float* __restrict__ x,
                 const float* __restrict__ w,       // (8,64)
                 const float* __restrict__ bias,    // (8,)
                 const float* __restrict__ gumbel,  // (B,2,G,28,28)
                 float* __restrict__ out_mask)      // (B,G,112,112)
{
    const int i   = blockIdx.x;   // coarse row 0..27
    const int b   = blockIdx.y;   // batch
    const int tid = threadIdx.x;

    __shared__ float sw[8 * 64];
    __shared__ float sb[8];
    __shared__ float sm[64 * 28];   // pooled means
    __shared__ float sl[8 * 28];    // logits
    __shared__ float sM[4 * 28];    // coarse mask (0/1)
    __shared__ unsigned int scnt;

    // 512 weights, 256 threads -> two loads per thread.
    sw[tid]       = w[tid];
    sw[tid + 256] = w[tid + 256];
    if (tid < 8)  sb[tid] = bias[tid];
    if (tid == 0) scnt = 0u;

    // ---- Phase 1: pooling (the HBM-bound term: 112 KB per CTA) ----
    // 64*28 = 1792 cells, 256 threads -> exactly 7 cells/thread; fully unrolled
    // so all 28 LDG.128 are front-batched (max MLP, DRAM latency hidden).
    {
        const float* xb = x + ((size_t)b * 64 * 112 + (size_t)i * 4) * 112;
        #pragma unroll
        for (int k = 0; k < 7; k++) {
            const int t = tid + k * 256;
            const int c = t / 28, j = t % 28;
            const float* p = xb + (size_t)c * (112 * 112) + j * 4;
            float s = 0.f;
            #pragma unroll
            for (int r = 0; r < 4; r++) {
                const float4 v = *reinterpret_cast<const float4*>(p + r * 112);
                s += v.x + v.y + v.z + v.w;
            }
            sm[c * 28 + j] = s * (1.0f / 16.0f);
        }
    }
    __syncthreads();

    // ---- Phase 2: logits (8 outputs x 28 cells) ----
    if (tid < 8 * 28) {
        const int o = tid / 28, j = tid % 28;
        float acc = sb[o];
        #pragma unroll
        for (int c = 0; c < 64; c++)
            acc += sw[o * 64 + c] * sm[c * 28 + j];
        sl[o * 28 + j] = acc;
    }
    __syncthreads();

    // ---- Phase 3: gumbel argmax -> coarse mask ----
    if (tid < 4 * 28) {
        const int g = tid / 28, j = tid % 28;
        const float g0 = gumbel[(((size_t)(b * 2 + 0) * 4 + g) * 28 + i) * 28 + j];
        const float g1 = gumbel[(((size_t)(b * 2 + 1) * 4 + g) * 28 + i) * 28 + j];
        const float v0 = sl[g * 28 + j]       + g0;
        const float v1 = sl[(4 + g) * 28 + j] + g1;
        const float m  = (v0 >= v1) ? 1.0f : 0.0f;   // jnp.argmax: first index wins ties
        sM[g * 28 + j] = m;
        if (m > 0.f) atomicAdd(&scnt, 1u);           // smem atomic only
    }
    __syncthreads();

    if (tid < 28) {
        const unsigned char a =
            (sM[tid] != 0.f) | (sM[28 + tid] != 0.f) |
            (sM[56 + tid] != 0.f) | (sM[84 + tid] != 0.f);
        gA[(b * 28 + i) * 28 + tid] = a;
    }
    if (tid == 0) g_cnt_mask[b * 28 + i] = scnt;     // plain store, no ATOMG

    // ---- Phase 4: fine mask, float4 stores (4 groups x 4 rows x 28 float4) ----
    for (int t = tid; t < 4 * 4 * 28; t += 256) {
        const int g  = t / 112;          // group
        const int r  = (t / 28) & 3;     // fine row within block
        const int cj = t % 28;           // coarse col -> fine cols 4cj..4cj+3
        const float v = sM[g * 28 + cj];
        float4* dst = reinterpret_cast<float4*>(
            out_mask + (((size_t)(b * 4 + g) * 112) + (i * 4 + r)) * 112) + cj;
        *dst = make_float4(v, v, v, v);
    }
}

// Dilation. A fine pixel's 3x3 window touches at most a 2x2 block of coarse
// cells (the neighbor cell only at 4x4-block-edge pixels). All G channels equal.
// Grid (112, 32), 128 threads; thread t<112: g=t/28, cj=t%28 -> one float4.
__global__ __launch_bounds__(128)
void k_dil(float* __restrict__ out_dil)   // (B,G,112,112)
{
    const int h = blockIdx.x;
    const int b = blockIdx.y;
    __shared__ unsigned int scnt;
    if (threadIdx.x == 0) scnt = 0u;
    __syncthreads();

    const int t = threadIdx.x;
    if (t < 112) {
        const int g  = t / 28;
        const int cj = t % 28;
        const int ci = h >> 2;
        const int r0 = ((h & 3) == 0 && ci > 0 ) ? ci - 1 : ci;
        const int r1 = ((h & 3) == 3 && ci < 27) ? ci + 1 : ci;
        const unsigned char* Ab = gA + (size_t)b * 28 * 28;
        const unsigned char mid = Ab[r0 * 28 + cj] | Ab[r1 * 28 + cj];
        // left edge pixel (col 4cj) may also see coarse col cj-1; right edge cj+1
        const unsigned char lft = (cj > 0 ) ? (unsigned char)(mid | Ab[r0 * 28 + cj - 1] | Ab[r1 * 28 + cj - 1]) : mid;
        const unsigned char rgt = (cj < 27) ? (unsigned char)(mid | Ab[r0 * 28 + cj + 1] | Ab[r1 * 28 + cj + 1]) : mid;
        const float4 v = make_float4(lft ? 1.f : 0.f, mid ? 1.f : 0.f,
                                     mid ? 1.f : 0.f, rgt ? 1.f : 0.f);
        float4* dst = reinterpret_cast<float4*>(
            out_dil + (((size_t)(b * 4 + g) * 112) + h) * 112) + cj;
        *dst = v;
        if (g == 0) {
            const unsigned int c = (lft ? 1u : 0u) + (mid ? 2u : 0u) + (rgt ? 1u : 0u);
            if (c) atomicAdd(&scnt, c);  // smem atomic only
        }
    }
    __syncthreads();
    if (threadIdx.x == 0) g_cnt_dil[b * 112 + h] = scnt;
}

// Single-CTA reduction of the per-row partial counts + scalar outputs.
__global__ __launch_bounds__(256)
void k_fin(float* __restrict__ out_scal) {
    __shared__ unsigned int s1[256], s2[256];
    const int tid = threadIdx.x;
    unsigned int a = 0, d = 0;
    for (int t = tid; t < B_ * MH_; t += 256) a += g_cnt_mask[t];
    for (int t = tid; t < B_ * H_;  t += 256) d += g_cnt_dil[t];
    s1[tid] = a; s2[tid] = d;
    __syncthreads();
    for (int s = 128; s > 0; s >>= 1) {
        if (tid < s) { s1[tid] += s1[tid + s]; s2[tid] += s2[tid + s]; }
        __syncthreads();
    }
    if (tid == 0) {
        // sparsity: fine mean == coarse mean (4x repeat preserves mean)
        out_scal[0] = (float)s1[0] / (float)(B_ * G_ * MH_ * MH_);
        // sparsity_dil: identical across the G output channels
        out_scal[1] = (float)s2[0] / (float)(B_ * H_ * H_);
        // flops = C*mh*mw + (8*64 + 64)*mh*mw = 501760
        out_scal[2] = 501760.0f;
    }
}

extern "C" void kernel_launch(void* const* d_in, const int* in_sizes, int n_in,
                              void* d_out, int out_size)
{
    const float* x      = (const float*)d_in[0];  // (32,64,112,112)
    const float* w      = (const float*)d_in[1];  // (8,64)
    const float* bias   = (const float*)d_in[2];  // (8,)
    const float* gumbel = (const float*)d_in[3];  // (32,2,4,28,28)
    // d_in[4] = temperature: irrelevant to argmax forward values

    float* out = (float*)d_out;
    // Flattened tuple layout: [mask (N) | mask_dil (N) | sparsity, sparsity_dil, flops]
    const long long N = ((long long)out_size - 3) / 2;   // = 32*4*112*112
    float* out_mask = out;
    float* out_dil  = out + N;
    float* out_scal = out + 2 * N;

    {
        dim3 grid(MH_, B_);
        k_pool_mask<<<grid, 256>>>(x, w, bias, gumbel, out_mask);
    }
    {
        dim3 grid(H_, B_);
        k_dil<<<grid, 128>>>(out_dil);
    }
    k_fin<<<1, 256>>>(out_scal);
}